// round 1
// baseline (speedup 1.0000x reference)
#include <cuda_runtime.h>
#include <math.h>

// Problem shape (fixed for this benchmark instance)
#define BB 16
#define TT 2048
#define DD 1024
#define NROW (BB*TT)

// Scratch (device globals; no allocation allowed)
__device__ float g_alphas[NROW];
__device__ float g_coefA[NROW];
__device__ float g_coefR[NROW];
__device__ int   g_firepos[NROW];
__device__ int   g_nf[BB];
__device__ int   g_len[BB];

// ---------------- Phase 1: alphas[b,t] = sigmoid(hs[b,t,:].w + bias) * mask[b,t]
__global__ void k_alphas(const float* __restrict__ hs,
                         const float* __restrict__ mask,
                         const float* __restrict__ w,
                         const float* __restrict__ bias) {
    int warp = (blockIdx.x * blockDim.x + threadIdx.x) >> 5;
    int lane = threadIdx.x & 31;
    if (warp >= NROW) return;

    const float4* row = reinterpret_cast<const float4*>(hs + (size_t)warp * DD);
    const float4* w4  = reinterpret_cast<const float4*>(w);

    float acc = 0.0f;
#pragma unroll
    for (int i = 0; i < 8; i++) {
        float4 h  = row[lane + 32 * i];
        float4 ww = __ldg(&w4[lane + 32 * i]);
        acc = fmaf(h.x, ww.x, acc);
        acc = fmaf(h.y, ww.y, acc);
        acc = fmaf(h.z, ww.z, acc);
        acc = fmaf(h.w, ww.w, acc);
    }
#pragma unroll
    for (int o = 16; o > 0; o >>= 1)
        acc += __shfl_down_sync(0xffffffffu, acc, o);

    if (lane == 0) {
        float x = acc + bias[0];
        float s = 1.0f / (1.0f + expf(-x));
        g_alphas[warp] = s * mask[warp];
    }
}

// ---------------- Phase 2: sequential integrate-and-fire scan (per batch)
// Replicates the reference's f32 op order exactly:
//   dist = 1 - integ; s = integ + a; fire = s > 0.95f;
//   cur = fire ? dist : a; integ = fire ? s - 1.0f : s; residual = a - cur
__global__ void k_scan() {
    int b = threadIdx.x;
    if (b >= BB) return;

    const float4* al4 = reinterpret_cast<const float4*>(g_alphas + b * TT);
    float integ = 0.0f;
    int nf = 0;
    double asum = 0.0;

    for (int t0 = 0; t0 < TT; t0 += 8) {
        float buf[8];
        float4 v0 = al4[(t0 >> 2) + 0];
        float4 v1 = al4[(t0 >> 2) + 1];
        buf[0]=v0.x; buf[1]=v0.y; buf[2]=v0.z; buf[3]=v0.w;
        buf[4]=v1.x; buf[5]=v1.y; buf[6]=v1.z; buf[7]=v1.w;
#pragma unroll
        for (int j = 0; j < 8; j++) {
            int t = t0 + j;
            float a = buf[j];
            float dist = 1.0f - integ;
            float s = integ + a;
            bool fire = (s > 0.95f);
            float cur = fire ? dist : a;
            g_coefA[b * TT + t] = cur;
            if (fire) {
                g_coefR[b * TT + t] = a - cur;   // frame_next coefficient
                g_firepos[b * TT + nf] = t;
                nf++;
                integ = s - 1.0f;                 // exact (Sterbenz)
            } else {
                integ = s;
            }
            asum += (double)a;
        }
    }
    g_nf[b] = nf;
    float fsum = (float)asum;
    g_len[b] = (int)rintf(fsum);                  // round-half-to-even like jnp.round
}

// ---------------- Phase 3: gather segments into packed output rows + mask
__global__ void k_gather(const float* __restrict__ hs,
                         float* __restrict__ out,
                         float* __restrict__ omask) {
    int k = blockIdx.x;       // output row index within batch (0..TT-1)
    int b = blockIdx.y;
    int tid = threadIdx.x;    // 256 threads, 4 floats each

    if (tid == 0)
        omask[b * TT + k] = (k < g_len[b]) ? 1.0f : 0.0f;

    float4* orow = reinterpret_cast<float4*>(out + ((size_t)(b * TT + k)) * DD);
    int nf = g_nf[b];

    if (k >= nf) {
        orow[tid] = make_float4(0.f, 0.f, 0.f, 0.f);
        return;
    }

    int tend  = g_firepos[b * TT + k];
    int tprev = (k > 0) ? g_firepos[b * TT + k - 1] : -1;

    float4 acc = make_float4(0.f, 0.f, 0.f, 0.f);

    if (k > 0) {
        // residual carried from previous fire row
        float r = g_coefR[b * TT + tprev];
        const float4* h = reinterpret_cast<const float4*>(hs + ((size_t)(b * TT + tprev)) * DD);
        float4 v = h[tid];
        acc.x = r * v.x; acc.y = r * v.y; acc.z = r * v.z; acc.w = r * v.w;
    }

    for (int t = tprev + 1; t <= tend; t++) {
        float c = g_coefA[b * TT + t];
        const float4* h = reinterpret_cast<const float4*>(hs + ((size_t)(b * TT + t)) * DD);
        float4 v = h[tid];
        acc.x = fmaf(c, v.x, acc.x);
        acc.y = fmaf(c, v.y, acc.y);
        acc.z = fmaf(c, v.z, acc.z);
        acc.w = fmaf(c, v.w, acc.w);
    }

    orow[tid] = acc;
}

extern "C" void kernel_launch(void* const* d_in, const int* in_sizes, int n_in,
                              void* d_out, int out_size) {
    const float* hs   = (const float*)d_in[0];   // [B,T,D]
    const float* mask = (const float*)d_in[1];   // [B,1,T]
    const float* w    = (const float*)d_in[2];   // [D]
    const float* bias = (const float*)d_in[3];   // scalar

    float* out   = (float*)d_out;                 // [B,T,D]
    float* omask = (float*)d_out + (size_t)BB * TT * DD;  // [B,1,T] as 0/1 floats

    // Phase 1: 1 warp per (b,t) row
    {
        int warpsPerBlock = 8;
        int blocks = NROW / warpsPerBlock;  // 4096
        k_alphas<<<blocks, warpsPerBlock * 32>>>(hs, mask, w, bias);
    }
    // Phase 2: one thread per batch, sequential scan
    k_scan<<<1, 32>>>();
    // Phase 3: one block per output row
    {
        dim3 grid(TT, BB);
        k_gather<<<grid, 256>>>(hs, out, omask);
    }
}

// round 2
// speedup vs baseline: 1.5471x; 1.5471x over previous
#include <cuda_runtime.h>
#include <math.h>

// Problem shape (fixed for this benchmark instance)
#define BB 16
#define TT 2048
#define DD 1024
#define NROW (BB*TT)

// Scratch (device globals; no allocation allowed)
__device__ float g_alphas[NROW];
__device__ float g_curF[NROW];     // coefficient of the fire row itself (dist_completion)
__device__ float g_residF[NROW];   // residual carried to next segment (alpha - cur)
__device__ int   g_firepos[NROW];  // time index of k-th fire in batch b
__device__ int   g_nf[BB];
__device__ int   g_len[BB];

// ---------------- Phase 1: alphas[b,t] = sigmoid(hs[b,t,:].w + bias) * mask[b,t]
__global__ void k_alphas(const float* __restrict__ hs,
                         const float* __restrict__ mask,
                         const float* __restrict__ w,
                         const float* __restrict__ bias) {
    int warp = (blockIdx.x * blockDim.x + threadIdx.x) >> 5;
    int lane = threadIdx.x & 31;
    if (warp >= NROW) return;

    const float4* row = reinterpret_cast<const float4*>(hs + (size_t)warp * DD);
    const float4* w4  = reinterpret_cast<const float4*>(w);

    float acc = 0.0f;
#pragma unroll
    for (int i = 0; i < 8; i++) {
        float4 h  = row[lane + 32 * i];
        float4 ww = __ldg(&w4[lane + 32 * i]);
        acc = fmaf(h.x, ww.x, acc);
        acc = fmaf(h.y, ww.y, acc);
        acc = fmaf(h.z, ww.z, acc);
        acc = fmaf(h.w, ww.w, acc);
    }
#pragma unroll
    for (int o = 16; o > 0; o >>= 1)
        acc += __shfl_down_sync(0xffffffffu, acc, o);

    if (lane == 0) {
        float x = acc + bias[0];
        float s = 1.0f / (1.0f + expf(-x));
        g_alphas[warp] = s * mask[warp];
    }
}

// ---------------- Phase 2: sequential integrate-and-fire scan (per batch)
// Bit-identical op order to the reference:
//   s = integ + a; fire = s > 0.95f;
//   cur = fire ? (1 - integ) : a; integ = fire ? s - 1.0f : s  (exact by Sterbenz)
// Only fire events are stored; interior coefficients == alpha (already in g_alphas).
__global__ void k_scan() {
    int b = threadIdx.x;
    if (b >= BB) return;

    const float4* al4 = reinterpret_cast<const float4*>(g_alphas + b * TT);
    const int base = b * TT;

    float integ = 0.0f;
    int nf = 0;

    // double-buffered prefetch of 8 alphas
    float4 p0 = al4[0], p1 = al4[1];

    for (int t0 = 0; t0 < TT; t0 += 8) {
        float buf[8];
        buf[0]=p0.x; buf[1]=p0.y; buf[2]=p0.z; buf[3]=p0.w;
        buf[4]=p1.x; buf[5]=p1.y; buf[6]=p1.z; buf[7]=p1.w;
        if (t0 + 8 < TT) {
            p0 = al4[(t0 >> 2) + 2];
            p1 = al4[(t0 >> 2) + 3];
        }
#pragma unroll
        for (int j = 0; j < 8; j++) {
            float a = buf[j];
            float dist = 1.0f - integ;   // off critical path
            float s = integ + a;         // FADD (4)
            bool fire = (s > 0.95f);     // FSETP guard (13)
            if (fire) {                  // short predicated arm (~50% rate)
                g_firepos[base + nf] = t0 + j;
                g_curF  [base + nf] = dist;
                g_residF[base + nf] = a - dist;
                nf++;
            }
            integ = fire ? (s - 1.0f) : s;  // FSEL (4); s-1 exact, off path
        }
    }
    g_nf[b] = nf;
}

// ---------------- Phase 2b: label lengths + output mask (parallel, per batch)
__global__ void k_lens(float* __restrict__ omask) {
    __shared__ double red[256];
    int b = blockIdx.x;
    int tid = threadIdx.x;

    const float4* al4 = reinterpret_cast<const float4*>(g_alphas + b * TT);
    float4 v0 = al4[tid];
    float4 v1 = al4[tid + 256];
    double s = (double)v0.x + v0.y + v0.z + v0.w
             + (double)v1.x + v1.y + v1.z + v1.w;
    red[tid] = s;
    __syncthreads();
    for (int o = 128; o > 0; o >>= 1) {
        if (tid < o) red[tid] += red[tid + o];
        __syncthreads();
    }
    __shared__ int s_len;
    if (tid == 0) {
        float fsum = (float)red[0];
        int len = (int)rintf(fsum);   // round-half-to-even like jnp.round
        g_len[b] = len;
        s_len = len;
    }
    __syncthreads();
    int len = s_len;
    // write new_masks as 0/1 floats
    float4* om4 = reinterpret_cast<float4*>(omask + b * TT);
#pragma unroll
    for (int i = 0; i < 2; i++) {
        int k = (tid + i * 256) * 4;
        float4 m;
        m.x = (k + 0 < len) ? 1.0f : 0.0f;
        m.y = (k + 1 < len) ? 1.0f : 0.0f;
        m.z = (k + 2 < len) ? 1.0f : 0.0f;
        m.w = (k + 3 < len) ? 1.0f : 0.0f;
        om4[tid + i * 256] = m;
    }
}

// ---------------- Phase 3: gather segments into packed output rows
__global__ void k_gather(const float* __restrict__ hs,
                         float* __restrict__ out) {
    int k = blockIdx.x;       // output row index within batch (0..TT-1)
    int b = blockIdx.y;
    int tid = threadIdx.x;    // 256 threads, 4 floats each

    float4* orow = reinterpret_cast<float4*>(out + ((size_t)(b * TT + k)) * DD);

    if (k >= g_nf[b]) {
        orow[tid] = make_float4(0.f, 0.f, 0.f, 0.f);
        return;
    }

    const int base = b * TT;
    int tend  = g_firepos[base + k];
    int tprev = (k > 0) ? g_firepos[base + k - 1] : -1;

    float4 acc = make_float4(0.f, 0.f, 0.f, 0.f);

    if (k > 0) {
        // residual carried from previous fire row
        float r = g_residF[base + k - 1];
        const float4* h = reinterpret_cast<const float4*>(hs + ((size_t)(base + tprev)) * DD);
        float4 v = h[tid];
        acc.x = r * v.x; acc.y = r * v.y; acc.z = r * v.z; acc.w = r * v.w;
    }

    // interior rows: coefficient == alpha
    for (int t = tprev + 1; t < tend; t++) {
        float c = g_alphas[base + t];
        const float4* h = reinterpret_cast<const float4*>(hs + ((size_t)(base + t)) * DD);
        float4 v = h[tid];
        acc.x = fmaf(c, v.x, acc.x);
        acc.y = fmaf(c, v.y, acc.y);
        acc.z = fmaf(c, v.z, acc.z);
        acc.w = fmaf(c, v.w, acc.w);
    }

    // fire row itself: coefficient == dist_completion
    {
        float c = g_curF[base + k];
        const float4* h = reinterpret_cast<const float4*>(hs + ((size_t)(base + tend)) * DD);
        float4 v = h[tid];
        acc.x = fmaf(c, v.x, acc.x);
        acc.y = fmaf(c, v.y, acc.y);
        acc.z = fmaf(c, v.z, acc.z);
        acc.w = fmaf(c, v.w, acc.w);
    }

    orow[tid] = acc;
}

extern "C" void kernel_launch(void* const* d_in, const int* in_sizes, int n_in,
                              void* d_out, int out_size) {
    const float* hs   = (const float*)d_in[0];   // [B,T,D]
    const float* mask = (const float*)d_in[1];   // [B,1,T]
    const float* w    = (const float*)d_in[2];   // [D]
    const float* bias = (const float*)d_in[3];   // scalar

    float* out   = (float*)d_out;                           // [B,T,D]
    float* omask = (float*)d_out + (size_t)BB * TT * DD;    // [B,1,T] as 0/1 floats

    // Phase 1: 1 warp per (b,t) row
    {
        int warpsPerBlock = 8;
        int blocks = NROW / warpsPerBlock;  // 4096
        k_alphas<<<blocks, warpsPerBlock * 32>>>(hs, mask, w, bias);
    }
    // Phase 2: one thread per batch, sequential scan (fire events only)
    k_scan<<<1, 32>>>();
    // Phase 2b: lengths + output mask (parallel)
    k_lens<<<BB, 256>>>(omask);
    // Phase 3: one block per output row
    {
        dim3 grid(TT, BB);
        k_gather<<<grid, 256>>>(hs, out);
    }
}

// round 5
// speedup vs baseline: 2.2570x; 1.4589x over previous
#include <cuda_runtime.h>
#include <math.h>

// Problem shape (fixed for this benchmark instance)
#define BB 16
#define TT 2048
#define DD 1024
#define NROW (BB*TT)

// Scratch (device globals; no allocation allowed)
__device__ float  g_alphas[NROW];
__device__ float4 g_events[NROW];  // {curF, residF, t_as_float_bits, pad} per fire, packed
__device__ int    g_nf[BB];
__device__ int    g_len[BB];

// ---------------- Phase 1: alphas[b,t] = sigmoid(hs[b,t,:].w + bias) * mask[b,t]
__global__ void k_alphas(const float* __restrict__ hs,
                         const float* __restrict__ mask,
                         const float* __restrict__ w,
                         const float* __restrict__ bias) {
    int warp = (blockIdx.x * blockDim.x + threadIdx.x) >> 5;
    int lane = threadIdx.x & 31;
    if (warp >= NROW) return;

    const float4* row = reinterpret_cast<const float4*>(hs + (size_t)warp * DD);
    const float4* w4  = reinterpret_cast<const float4*>(w);

    float acc = 0.0f;
#pragma unroll
    for (int i = 0; i < 8; i++) {
        float4 h  = row[lane + 32 * i];
        float4 ww = __ldg(&w4[lane + 32 * i]);
        acc = fmaf(h.x, ww.x, acc);
        acc = fmaf(h.y, ww.y, acc);
        acc = fmaf(h.z, ww.z, acc);
        acc = fmaf(h.w, ww.w, acc);
    }
#pragma unroll
    for (int o = 16; o > 0; o >>= 1)
        acc += __shfl_down_sync(0xffffffffu, acc, o);

    if (lane == 0) {
        float x = acc + bias[0];
        float s = 1.0f / (1.0f + expf(-x));
        g_alphas[warp] = s * mask[warp];
    }
}

// ---------------- Phase 2: sequential integrate-and-fire scan
// One batch per BLOCK (single active thread) -> no cross-batch branch coupling,
// single-wavefront stores. Branch-free body: unconditional STG.128 of the
// candidate fire event to slot nf; nf advances only on fire (overwrite otherwise).
// Fire arithmetic is bit-identical to the reference:
//   s = integ + a; fire = s > 0.95f; integ = fire ? s - 1.0f : s  (Sterbenz-exact)
__global__ void k_scan() {
    if (threadIdx.x != 0) return;
    int b = blockIdx.x;

    const float4* al4 = reinterpret_cast<const float4*>(g_alphas + b * TT);
    float4* ev = g_events + b * TT;

    float integ = 0.0f;
    int nf = 0;

    float4 p0 = al4[0], p1 = al4[1];

    for (int t0 = 0; t0 < TT; t0 += 8) {
        float buf[8];
        buf[0]=p0.x; buf[1]=p0.y; buf[2]=p0.z; buf[3]=p0.w;
        buf[4]=p1.x; buf[5]=p1.y; buf[6]=p1.z; buf[7]=p1.w;
        if (t0 + 8 < TT) {
            p0 = al4[(t0 >> 2) + 2];
            p1 = al4[(t0 >> 2) + 3];
        }
#pragma unroll
        for (int j = 0; j < 8; j++) {
            float a = buf[j];
            float dist = 1.0f - integ;       // off critical path
            float s = integ + a;             // FADD (4) — critical
            bool fire = (s > 0.95f);         // FSETP (4, pred-as-data) — critical
            float4 e;
            e.x = dist;                      // cur at fire
            e.y = a - dist;                  // residual to next segment
            e.z = __int_as_float(t0 + j);    // fire time index
            e.w = 0.0f;
            ev[nf] = e;                      // unconditional STG.128
            nf += fire ? 1 : 0;
            integ = fire ? (s - 1.0f) : s;   // FSEL (4) — critical
        }
    }
    g_nf[b] = nf;
}

// ---------------- Phase 2b: label lengths + output mask (parallel, per batch)
__global__ void k_lens(float* __restrict__ omask) {
    __shared__ double red[256];
    int b = blockIdx.x;
    int tid = threadIdx.x;

    const float4* al4 = reinterpret_cast<const float4*>(g_alphas + b * TT);
    float4 v0 = al4[tid];
    float4 v1 = al4[tid + 256];
    double s = (double)v0.x + v0.y + v0.z + v0.w
             + (double)v1.x + v1.y + v1.z + v1.w;
    red[tid] = s;
    __syncthreads();
    for (int o = 128; o > 0; o >>= 1) {
        if (tid < o) red[tid] += red[tid + o];
        __syncthreads();
    }
    __shared__ int s_len;
    if (tid == 0) {
        float fsum = (float)red[0];
        int len = (int)rintf(fsum);   // round-half-to-even like jnp.round
        g_len[b] = len;
        s_len = len;
    }
    __syncthreads();
    int len = s_len;
    float4* om4 = reinterpret_cast<float4*>(omask + b * TT);
#pragma unroll
    for (int i = 0; i < 2; i++) {
        int k = (tid + i * 256) * 4;
        float4 m;
        m.x = (k + 0 < len) ? 1.0f : 0.0f;
        m.y = (k + 1 < len) ? 1.0f : 0.0f;
        m.z = (k + 2 < len) ? 1.0f : 0.0f;
        m.w = (k + 3 < len) ? 1.0f : 0.0f;
        om4[tid + i * 256] = m;
    }
}

// ---------------- Phase 3: gather segments into packed output rows
__global__ void k_gather(const float* __restrict__ hs,
                         float* __restrict__ out) {
    int k = blockIdx.x;       // output row index within batch (0..TT-1)
    int b = blockIdx.y;
    int tid = threadIdx.x;    // 256 threads, 4 floats each

    float4* orow = reinterpret_cast<float4*>(out + ((size_t)(b * TT + k)) * DD);

    if (k >= g_nf[b]) {
        orow[tid] = make_float4(0.f, 0.f, 0.f, 0.f);
        return;
    }

    const int base = b * TT;
    float4 evk = g_events[base + k];
    int tend = __float_as_int(evk.z);

    float4 acc = make_float4(0.f, 0.f, 0.f, 0.f);
    int tprev = -1;

    if (k > 0) {
        float4 evp = g_events[base + k - 1];
        tprev = __float_as_int(evp.z);
        float r = evp.y;   // residual carried from previous fire row
        const float4* h = reinterpret_cast<const float4*>(hs + ((size_t)(base + tprev)) * DD);
        float4 v = h[tid];
        acc.x = r * v.x; acc.y = r * v.y; acc.z = r * v.z; acc.w = r * v.w;
    }

    // interior rows: coefficient == alpha
    for (int t = tprev + 1; t < tend; t++) {
        float c = g_alphas[base + t];
        const float4* h = reinterpret_cast<const float4*>(hs + ((size_t)(base + t)) * DD);
        float4 v = h[tid];
        acc.x = fmaf(c, v.x, acc.x);
        acc.y = fmaf(c, v.y, acc.y);
        acc.z = fmaf(c, v.z, acc.z);
        acc.w = fmaf(c, v.w, acc.w);
    }

    // fire row itself: coefficient == dist_completion
    {
        float c = evk.x;
        const float4* h = reinterpret_cast<const float4*>(hs + ((size_t)(base + tend)) * DD);
        float4 v = h[tid];
        acc.x = fmaf(c, v.x, acc.x);
        acc.y = fmaf(c, v.y, acc.y);
        acc.z = fmaf(c, v.z, acc.z);
        acc.w = fmaf(c, v.w, acc.w);
    }

    orow[tid] = acc;
}

extern "C" void kernel_launch(void* const* d_in, const int* in_sizes, int n_in,
                              void* d_out, int out_size) {
    const float* hs   = (const float*)d_in[0];   // [B,T,D]
    const float* mask = (const float*)d_in[1];   // [B,1,T]
    const float* w    = (const float*)d_in[2];   // [D]
    const float* bias = (const float*)d_in[3];   // scalar

    float* out   = (float*)d_out;                           // [B,T,D]
    float* omask = (float*)d_out + (size_t)BB * TT * DD;    // [B,1,T] as 0/1 floats

    // Phase 1: 1 warp per (b,t) row
    {
        int warpsPerBlock = 8;
        int blocks = NROW / warpsPerBlock;  // 4096
        k_alphas<<<blocks, warpsPerBlock * 32>>>(hs, mask, w, bias);
    }
    // Phase 2: one block per batch, single-thread branch-free scan
    k_scan<<<BB, 32>>>();
    // Phase 2b: lengths + output mask (parallel)
    k_lens<<<BB, 256>>>(omask);
    // Phase 3: one block per output row
    {
        dim3 grid(TT, BB);
        k_gather<<<grid, 256>>>(hs, out);
    }
}

// round 6
// speedup vs baseline: 2.9519x; 1.3079x over previous
#include <cuda_runtime.h>
#include <math.h>

// Problem shape (fixed for this benchmark instance)
#define BB 16
#define TT 2048
#define DD 1024
#define NROW (BB*TT)

// Scratch (device globals; no allocation allowed)
__device__ float  g_alphas[NROW];
__device__ float4 g_events[NROW];  // {curF, residF, t_as_int_bits, pad} per fire, packed
__device__ int    g_nf[BB];

// ---------------- Phase 1: alphas[b,t] = sigmoid(hs[b,t,:].w + bias) * mask[b,t]
__global__ void k_alphas(const float* __restrict__ hs,
                         const float* __restrict__ mask,
                         const float* __restrict__ w,
                         const float* __restrict__ bias) {
    int warp = (blockIdx.x * blockDim.x + threadIdx.x) >> 5;
    int lane = threadIdx.x & 31;
    if (warp >= NROW) return;

    const float4* row = reinterpret_cast<const float4*>(hs + (size_t)warp * DD);
    const float4* w4  = reinterpret_cast<const float4*>(w);

    float acc0 = 0.0f, acc1 = 0.0f;
#pragma unroll
    for (int i = 0; i < 8; i += 2) {
        float4 h0 = row[lane + 32 * i];
        float4 h1 = row[lane + 32 * (i + 1)];
        float4 w0 = __ldg(&w4[lane + 32 * i]);
        float4 w1 = __ldg(&w4[lane + 32 * (i + 1)]);
        acc0 = fmaf(h0.x, w0.x, acc0);
        acc0 = fmaf(h0.y, w0.y, acc0);
        acc0 = fmaf(h0.z, w0.z, acc0);
        acc0 = fmaf(h0.w, w0.w, acc0);
        acc1 = fmaf(h1.x, w1.x, acc1);
        acc1 = fmaf(h1.y, w1.y, acc1);
        acc1 = fmaf(h1.z, w1.z, acc1);
        acc1 = fmaf(h1.w, w1.w, acc1);
    }
    float acc = acc0 + acc1;
#pragma unroll
    for (int o = 16; o > 0; o >>= 1)
        acc += __shfl_down_sync(0xffffffffu, acc, o);

    if (lane == 0) {
        float x = acc + bias[0];
        float s = 1.0f / (1.0f + expf(-x));
        g_alphas[warp] = s * mask[warp];
    }
}

// ---------------- Phase 2 (fused): stage alphas to smem, serial scan (warp 0),
// lens + mask (warps 1-3, concurrent), event flush (all threads).
// Fire arithmetic bit-identical to the reference:
//   s = integ + a; fire = s > 0.95f;
//   cur = fire ? (1 - integ) : a; integ = fire ? s - 1.0f : s  (Sterbenz-exact)
__global__ void k_scan(float* __restrict__ omask) {
    __shared__ float  s_al[TT];        // 8 KB
    __shared__ float4 s_ev[TT];        // 32 KB
    __shared__ double s_part[128];     // 1 KB
    __shared__ int    s_nf;
    __shared__ int    s_len;

    int b   = blockIdx.x;
    int tid = threadIdx.x;
    int wid = tid >> 5;

    // Cooperative stage: 2048 floats = 512 float4, 4 per thread. Also partial sums.
    const float4* al4 = reinterpret_cast<const float4*>(g_alphas + b * TT);
    float4* s_al4 = reinterpret_cast<float4*>(s_al);
    double psum = 0.0;
#pragma unroll
    for (int i = 0; i < 4; i++) {
        int idx = tid + i * 128;
        float4 v = al4[idx];
        s_al4[idx] = v;
        psum += (double)v.x + v.y + v.z + v.w;
    }
    s_part[tid] = psum;
    __syncthreads();

    if (wid == 0) {
        if (tid == 0) {
            // -------- serial integrate-and-fire scan (from smem) --------
            float integ = 0.0f;
            int nf = 0;
            float4 p = s_al4[0];
            for (int t0 = 0; t0 < TT; t0 += 4) {
                float buf[4];
                buf[0] = p.x; buf[1] = p.y; buf[2] = p.z; buf[3] = p.w;
                if (t0 + 4 < TT) p = s_al4[(t0 >> 2) + 1];
#pragma unroll
                for (int j = 0; j < 4; j++) {
                    float a = buf[j];
                    float dist = 1.0f - integ;      // off critical path
                    float s = integ + a;            // FADD — critical
                    bool fire = (s > 0.95f);        // FSETP — critical
                    float4 e;
                    e.x = dist;                     // cur at fire
                    e.y = a - dist;                 // residual to next segment
                    e.z = __int_as_float(t0 + j);   // fire time index
                    e.w = 0.0f;
                    s_ev[nf] = e;                   // unconditional STS.128
                    nf += fire ? 1 : 0;
                    integ = fire ? (s - 1.0f) : s;  // FSEL — critical
                }
            }
            s_nf = nf;
        }
    } else if (wid == 1) {
        // -------- length reduction (concurrent with scan) --------
        int lane = tid & 31;
        double r = s_part[lane] + s_part[lane + 32]
                 + s_part[lane + 64] + s_part[lane + 96];
#pragma unroll
        for (int o = 16; o > 0; o >>= 1)
            r += __shfl_down_sync(0xffffffffu, r, o);
        if (lane == 0) {
            float fsum = (float)r;
            s_len = (int)rintf(fsum);   // round-half-to-even like jnp.round
        }
    }
    // warps 1-3 sync among themselves, then write the mask while warp 0 scans
    if (wid >= 1) {
        asm volatile("bar.sync 1, 96;" ::: "memory");
        int len = s_len;
        float4* om4 = reinterpret_cast<float4*>(omask + b * TT);
        int id = tid - 32;   // 0..95
        for (int i = id; i < TT / 4; i += 96) {
            int k = i * 4;
            float4 m;
            m.x = (k + 0 < len) ? 1.0f : 0.0f;
            m.y = (k + 1 < len) ? 1.0f : 0.0f;
            m.z = (k + 2 < len) ? 1.0f : 0.0f;
            m.w = (k + 3 < len) ? 1.0f : 0.0f;
            om4[i] = m;
        }
    }
    __syncthreads();

    // -------- coalesced event flush --------
    int nf = s_nf;
    float4* ev = g_events + b * TT;
    for (int i = tid; i < nf; i += 128)
        ev[i] = s_ev[i];
    if (tid == 0) g_nf[b] = nf;
}

// ---------------- Phase 3: gather segments into packed output rows
__global__ void k_gather(const float* __restrict__ hs,
                         float* __restrict__ out) {
    int k = blockIdx.x;       // output row index within batch (0..TT-1)
    int b = blockIdx.y;
    int tid = threadIdx.x;    // 256 threads, 4 floats each

    float4* orow = reinterpret_cast<float4*>(out + ((size_t)(b * TT + k)) * DD);

    if (k >= g_nf[b]) {
        orow[tid] = make_float4(0.f, 0.f, 0.f, 0.f);
        return;
    }

    const int base = b * TT;
    float4 evk = g_events[base + k];
    int tend = __float_as_int(evk.z);

    float4 acc = make_float4(0.f, 0.f, 0.f, 0.f);
    int tprev = -1;

    if (k > 0) {
        float4 evp = g_events[base + k - 1];
        tprev = __float_as_int(evp.z);
        float r = evp.y;   // residual carried from previous fire row
        const float4* h = reinterpret_cast<const float4*>(hs + ((size_t)(base + tprev)) * DD);
        float4 v = h[tid];
        acc.x = r * v.x; acc.y = r * v.y; acc.z = r * v.z; acc.w = r * v.w;
    }

    // interior rows: coefficient == alpha
    for (int t = tprev + 1; t < tend; t++) {
        float c = g_alphas[base + t];
        const float4* h = reinterpret_cast<const float4*>(hs + ((size_t)(base + t)) * DD);
        float4 v = h[tid];
        acc.x = fmaf(c, v.x, acc.x);
        acc.y = fmaf(c, v.y, acc.y);
        acc.z = fmaf(c, v.z, acc.z);
        acc.w = fmaf(c, v.w, acc.w);
    }

    // fire row itself: coefficient == dist_completion
    {
        float c = evk.x;
        const float4* h = reinterpret_cast<const float4*>(hs + ((size_t)(base + tend)) * DD);
        float4 v = h[tid];
        acc.x = fmaf(c, v.x, acc.x);
        acc.y = fmaf(c, v.y, acc.y);
        acc.z = fmaf(c, v.z, acc.z);
        acc.w = fmaf(c, v.w, acc.w);
    }

    orow[tid] = acc;
}

extern "C" void kernel_launch(void* const* d_in, const int* in_sizes, int n_in,
                              void* d_out, int out_size) {
    const float* hs   = (const float*)d_in[0];   // [B,T,D]
    const float* mask = (const float*)d_in[1];   // [B,1,T]
    const float* w    = (const float*)d_in[2];   // [D]
    const float* bias = (const float*)d_in[3];   // scalar

    float* out   = (float*)d_out;                           // [B,T,D]
    float* omask = (float*)d_out + (size_t)BB * TT * DD;    // [B,1,T] as 0/1 floats

    // Phase 1: 1 warp per (b,t) row
    {
        int warpsPerBlock = 8;
        int blocks = NROW / warpsPerBlock;  // 4096
        k_alphas<<<blocks, warpsPerBlock * 32>>>(hs, mask, w, bias);
    }
    // Phase 2 (fused): scan + lens + mask, one block per batch
    k_scan<<<BB, 128>>>(omask);
    // Phase 3: one block per output row
    {
        dim3 grid(TT, BB);
        k_gather<<<grid, 256>>>(hs, out);
    }
}